// round 10
// baseline (speedup 1.0000x reference)
#include <cuda_runtime.h>
#include <cuda_fp16.h>
#include <mma.h>
#include <cstdint>

using namespace nvcuda;

#define NROWS 8192
#define FEAT  128

// ---------------- scratch (no allocations allowed) ----------------
__device__ float  g_dinv[NROWS];
__device__ float  g_y [NROWS * FEAT];          // y = dinv*x, fp32 (k3 self-loop term)
__device__ __half g_yh[NROWS * FEAT];          // y in fp16 (GEMM B operand)
__device__ __half g_adjh[(size_t)NROWS * NROWS];  // adj in fp16 (GEMM A operand), 128 MB
__device__ float  g_hp[4][NROWS * FEAT];       // split-K partials of adj @ y

// ================= helpers =================
__device__ __forceinline__ void cp16s(void* dst, const void* src) {
    uint32_t s = (uint32_t)__cvta_generic_to_shared(dst);
    asm volatile("cp.async.cg.shared.global [%0], [%1], 16;" :: "r"(s), "l"(src));
}
__device__ __forceinline__ void cp_commit() { asm volatile("cp.async.commit_group;"); }
template <int n> __device__ __forceinline__ void cp_wait() {
    asm volatile("cp.async.wait_group %0;" :: "n"(n));
}
__device__ __forceinline__ uint32_t h2u(__half2 h) {
    uint32_t u;
    memcpy(&u, &h, 4);
    return u;
}

// =================================================================
// Kernel 1: rowsum(adj)+1 -> dinv ; adjh = fp16(adj) ; y = dinv*x ;
//           yh = fp16(y).  One block per row, 256 threads.
// =================================================================
__global__ __launch_bounds__(256) void k_rowsum_y(
    const float* __restrict__ adj, const float* __restrict__ x)
{
    const int row = blockIdx.x;
    const int t = threadIdx.x;
    const float4* a4 = reinterpret_cast<const float4*>(adj + (size_t)row * NROWS);
    __half* ah = g_adjh + (size_t)row * NROWS;

    float s = 0.f;
#pragma unroll
    for (int i = 0; i < 8; i++) {
        float4 v = a4[i * 256 + t];
        s += (v.x + v.y) + (v.z + v.w);
        uint2 pk = make_uint2(h2u(__floats2half2_rn(v.x, v.y)),
                              h2u(__floats2half2_rn(v.z, v.w)));
        *reinterpret_cast<uint2*>(ah + (size_t)(i * 256 + t) * 4) = pk;
    }
#pragma unroll
    for (int o = 16; o; o >>= 1) s += __shfl_xor_sync(0xffffffffu, s, o);

    __shared__ float ws[8];
    __shared__ float sdinv;
    if ((t & 31) == 0) ws[t >> 5] = s;
    __syncthreads();
    if (t < 32) {
        float v = (t < 8) ? ws[t] : 0.f;
#pragma unroll
        for (int o = 4; o; o >>= 1) v += __shfl_xor_sync(0xffffffffu, v, o);
        if (t == 0) {
            float d = rsqrtf(v + 1.0f);   // +1 self loop
            sdinv = d;
            g_dinv[row] = d;
        }
    }
    __syncthreads();
    const float d = sdinv;
    if (t < 32) {
        float4 xv = reinterpret_cast<const float4*>(x + (size_t)row * FEAT)[t];
        float4 yv;
        yv.x = d * xv.x; yv.y = d * xv.y; yv.z = d * xv.z; yv.w = d * xv.w;
        reinterpret_cast<float4*>(g_y + (size_t)row * FEAT)[t] = yv;
        uint2 pk = make_uint2(h2u(__floats2half2_rn(yv.x, yv.y)),
                              h2u(__floats2half2_rn(yv.z, yv.w)));
        *reinterpret_cast<uint2*>(g_yh + (size_t)row * FEAT + t * 4) = pk;
    }
}

// =================================================================
// Kernel 2: g_hp[split] = adjh[:, quarter] @ yh[quarter, :]  fp16 HMMA
// BM=64, BN=128, BK=32, 3-stage cp.async, split-K=4 (512 CTAs,
// ~3.4 resident CTAs/SM -> 6 warps/SMSP for latency hiding)
// =================================================================
constexpr int BM = 64;
constexpr int BK = 32;
constexpr int STAGES = 3;
constexpr int APITCH = 40;            // halfs (80B rows)
constexpr int BPITCH = FEAT + 8;      // 136 halfs (272B rows)
constexpr int SPLITK = 4;
constexpr int KPER = NROWS / SPLITK;  // 2048
constexpr int ITERS = KPER / BK;      // 64
constexpr int A_STAGE = BM * APITCH;  // halfs
constexpr int B_STAGE = BK * BPITCH;  // halfs
constexpr int SMEM_BYTES = STAGES * (A_STAGE + B_STAGE) * 2; // 41472

__global__ __launch_bounds__(256, 3) void k_gemm()
{
    extern __shared__ __half smem[];
    __half* As = smem;                         // [STAGES][BM][APITCH]
    __half* Bs = smem + STAGES * A_STAGE;      // [STAGES][BK][BPITCH]

    const int t = threadIdx.x;
    const int mtile = blockIdx.x >> 2;
    const int split = blockIdx.x & 3;
    const int rowBase = mtile * BM;
    const int kBase = split * KPER;

    auto load_stage = [&](int s, int kit) {
        const int k0 = kBase + kit * BK;
        // A tile: 64 rows x 32 halfs (64B/row) = 256 x 16B chunks, 1/thread
        {
            int r = t >> 2, c = (t & 3) * 8;
            cp16s(&As[s * A_STAGE + r * APITCH + c],
                  g_adjh + (size_t)(rowBase + r) * NROWS + k0 + c);
        }
        // B tile: 32 rows x 128 halfs (256B/row) = 512 chunks, 2/thread
#pragma unroll
        for (int i = 0; i < 2; i++) {
            int lin = t + i * 256;
            int r = lin >> 4, c = (lin & 15) * 8;
            cp16s(&Bs[s * B_STAGE + r * BPITCH + c],
                  g_yh + (size_t)(k0 + r) * FEAT + c);
        }
    };

#pragma unroll
    for (int p = 0; p < STAGES - 1; p++) { load_stage(p, p); cp_commit(); }

    const int wid = t >> 5;
    const int wm = wid >> 2;   // 0..1  (32-row slab)
    const int wn = wid & 3;    // 0..3  (32-col slab)

    wmma::fragment<wmma::accumulator, 16, 16, 16, float> acc[2][2];
#pragma unroll
    for (int i = 0; i < 2; i++)
#pragma unroll
        for (int j = 0; j < 2; j++) wmma::fill_fragment(acc[i][j], 0.0f);

    for (int it = 0; it < ITERS; it++) {
        cp_wait<STAGES - 2>();
        __syncthreads();                  // stage it ready; all warps done with stage it-1
        int pf = it + STAGES - 1;
        if (pf < ITERS) load_stage(pf % STAGES, pf);
        cp_commit();

        const __half* A = &As[(it % STAGES) * A_STAGE];
        const __half* B = &Bs[(it % STAGES) * B_STAGE];
#pragma unroll
        for (int kk = 0; kk < BK / 16; kk++) {
            wmma::fragment<wmma::matrix_a, 16, 16, 16, __half, wmma::row_major> af[2];
            wmma::fragment<wmma::matrix_b, 16, 16, 16, __half, wmma::row_major> bf[2];
#pragma unroll
            for (int i = 0; i < 2; i++)
                wmma::load_matrix_sync(af[i], A + (wm * 32 + i * 16) * APITCH + kk * 16, APITCH);
#pragma unroll
            for (int j = 0; j < 2; j++)
                wmma::load_matrix_sync(bf[j], B + (kk * 16) * BPITCH + wn * 32 + j * 16, BPITCH);
#pragma unroll
            for (int i = 0; i < 2; i++)
#pragma unroll
                for (int j = 0; j < 2; j++)
                    wmma::mma_sync(acc[i][j], af[i], bf[j], acc[i][j]);
        }
    }

#pragma unroll
    for (int i = 0; i < 2; i++)
#pragma unroll
        for (int j = 0; j < 2; j++)
            wmma::store_matrix_sync(
                &g_hp[split][(size_t)(rowBase + wm * 32 + i * 16) * FEAT + wn * 32 + j * 16],
                acc[i][j], FEAT, wmma::mem_row_major);
}

// =================================================================
// Kernel 3: h = dinv_i*((hp0+hp1+hp2+hp3) + y); z = h@W^T + b; L2-norm
// =================================================================
__global__ __launch_bounds__(256) void k_epilogue(
    const float* __restrict__ W, const float* __restrict__ bias,
    float* __restrict__ out)
{
    __shared__ float hs[64 * 132];
    const int t = threadIdx.x;
    const int row0 = blockIdx.x * 64;

#pragma unroll
    for (int i = 0; i < 8; i++) {
        int lin = t + i * 256;
        int r = lin >> 5, c = (lin & 31) * 4;
        size_t idx = (size_t)(row0 + r) * FEAT + c;
        float4 h0 = *reinterpret_cast<const float4*>(&g_hp[0][idx]);
        float4 h1 = *reinterpret_cast<const float4*>(&g_hp[1][idx]);
        float4 h2 = *reinterpret_cast<const float4*>(&g_hp[2][idx]);
        float4 h3 = *reinterpret_cast<const float4*>(&g_hp[3][idx]);
        float4 yv = *reinterpret_cast<const float4*>(&g_y[idx]);
        float d = g_dinv[row0 + r];
        float4 o;
        o.x = d * (((h0.x + h1.x) + (h2.x + h3.x)) + yv.x);
        o.y = d * (((h0.y + h1.y) + (h2.y + h3.y)) + yv.y);
        o.z = d * (((h0.z + h1.z) + (h2.z + h3.z)) + yv.z);
        o.w = d * (((h0.w + h1.w) + (h2.w + h3.w)) + yv.w);
        *reinterpret_cast<float4*>(&hs[r * 132 + c]) = o;
    }
    __syncthreads();

    const int wid = t >> 5, lane = t & 31;
    const int wm = wid >> 2, wn = wid & 3;

    wmma::fragment<wmma::accumulator, 16, 16, 8, float> acc[2][2];
#pragma unroll
    for (int i = 0; i < 2; i++)
#pragma unroll
        for (int j = 0; j < 2; j++) wmma::fill_fragment(acc[i][j], 0.0f);

    // z = h @ W^T : col_major view of row-major W, ld=FEAT  (tf32, tiny GEMM)
#pragma unroll
    for (int k0 = 0; k0 < FEAT; k0 += 8) {
        wmma::fragment<wmma::matrix_a, 16, 16, 8, wmma::precision::tf32, wmma::row_major> af[2];
        wmma::fragment<wmma::matrix_b, 16, 16, 8, wmma::precision::tf32, wmma::col_major> bf[2];
#pragma unroll
        for (int i = 0; i < 2; i++) {
            wmma::load_matrix_sync(af[i], &hs[(wm * 32 + i * 16) * 132 + k0], 132);
#pragma unroll
            for (int e = 0; e < af[i].num_elements; e++)
                af[i].x[e] = wmma::__float_to_tf32(af[i].x[e]);
        }
#pragma unroll
        for (int j = 0; j < 2; j++) {
            wmma::load_matrix_sync(bf[j], W + (size_t)(wn * 32 + j * 16) * FEAT + k0, FEAT);
#pragma unroll
            for (int e = 0; e < bf[j].num_elements; e++)
                bf[j].x[e] = wmma::__float_to_tf32(bf[j].x[e]);
        }
#pragma unroll
        for (int i = 0; i < 2; i++)
#pragma unroll
            for (int j = 0; j < 2; j++)
                wmma::mma_sync(acc[i][j], af[i], bf[j], acc[i][j]);
    }
    __syncthreads();

#pragma unroll
    for (int i = 0; i < 2; i++)
#pragma unroll
        for (int j = 0; j < 2; j++)
            wmma::store_matrix_sync(&hs[(wm * 32 + i * 16) * 132 + wn * 32 + j * 16],
                                    acc[i][j], 132, wmma::mem_row_major);
    __syncthreads();

    float4 bv = *reinterpret_cast<const float4*>(bias + lane * 4);
#pragma unroll
    for (int r8 = 0; r8 < 8; r8++) {
        int r = wid * 8 + r8;
        float4 z = *reinterpret_cast<float4*>(&hs[r * 132 + lane * 4]);
        z.x += bv.x; z.y += bv.y; z.z += bv.z; z.w += bv.w;
        float s = z.x * z.x + z.y * z.y + z.z * z.z + z.w * z.w;
#pragma unroll
        for (int o = 16; o; o >>= 1) s += __shfl_xor_sync(0xffffffffu, s, o);
        float inv = 1.0f / fmaxf(sqrtf(s), 1e-12f);
        float4 o4;
        o4.x = z.x * inv; o4.y = z.y * inv; o4.z = z.z * inv; o4.w = z.w * inv;
        *reinterpret_cast<float4*>(out + (size_t)(row0 + r) * FEAT + lane * 4) = o4;
    }
}

// =================================================================
// launch (graph-capturable, no allocs, default stream)
// inputs: x [8192,128], adj [8192,8192], W [128,128], b [128]
// =================================================================
extern "C" void kernel_launch(void* const* d_in, const int* in_sizes, int n_in,
                              void* d_out, int out_size)
{
    const float* x   = (const float*)d_in[0];
    const float* adj = (const float*)d_in[1];
    const float* W   = (const float*)d_in[2];
    const float* b   = (const float*)d_in[3];
    float* out = (float*)d_out;

    cudaStreamCaptureStatus cap = cudaStreamCaptureStatusNone;
    cudaStreamIsCapturing((cudaStream_t)0, &cap);
    if (cap == cudaStreamCaptureStatusNone) {
        cudaFuncSetAttribute(k_gemm, cudaFuncAttributeMaxDynamicSharedMemorySize,
                             SMEM_BYTES);
    }

    k_rowsum_y<<<NROWS, 256>>>(adj, x);
    k_gemm<<<(NROWS / BM) * SPLITK, 256, SMEM_BYTES>>>();
    k_epilogue<<<NROWS / 64, 256>>>(W, b, out);
}

// round 11
// speedup vs baseline: 1.1192x; 1.1192x over previous
#include <cuda_runtime.h>
#include <cuda_fp16.h>
#include <mma.h>
#include <cstdint>

using namespace nvcuda;

#define NROWS 8192
#define FEAT  128

// ---------------- scratch (no allocations allowed) ----------------
__device__ float  g_dinv[NROWS];
__device__ float  g_y [NROWS * FEAT];          // y = dinv*x, fp32 (k3 self-loop term)
__device__ __half g_yh[NROWS * FEAT];          // y in fp16 (GEMM B operand)
__device__ __half g_adjh[(size_t)NROWS * NROWS];  // adj in fp16 (GEMM A operand), 128 MB
__device__ float  g_hp[4][NROWS * FEAT];       // split-K partials of adj @ y

// ================= helpers =================
__device__ __forceinline__ void cp16s(void* dst, const void* src) {
    uint32_t s = (uint32_t)__cvta_generic_to_shared(dst);
    asm volatile("cp.async.cg.shared.global [%0], [%1], 16;" :: "r"(s), "l"(src));
}
__device__ __forceinline__ void cp_commit() { asm volatile("cp.async.commit_group;"); }
template <int n> __device__ __forceinline__ void cp_wait() {
    asm volatile("cp.async.wait_group %0;" :: "n"(n));
}
__device__ __forceinline__ uint32_t h2u(__half2 h) {
    uint32_t u;
    memcpy(&u, &h, 4);
    return u;
}

// =================================================================
// Kernel 1: rowsum(adj)+1 -> dinv ; adjh = fp16(adj) ; y = dinv*x ;
//           yh = fp16(y).  One block per row, 256 threads.
// =================================================================
__global__ __launch_bounds__(256) void k_rowsum_y(
    const float* __restrict__ adj, const float* __restrict__ x)
{
    const int row = blockIdx.x;
    const int t = threadIdx.x;
    const float4* a4 = reinterpret_cast<const float4*>(adj + (size_t)row * NROWS);
    __half* ah = g_adjh + (size_t)row * NROWS;

    float s = 0.f;
#pragma unroll
    for (int i = 0; i < 8; i++) {
        float4 v = a4[i * 256 + t];
        s += (v.x + v.y) + (v.z + v.w);
        uint2 pk = make_uint2(h2u(__floats2half2_rn(v.x, v.y)),
                              h2u(__floats2half2_rn(v.z, v.w)));
        *reinterpret_cast<uint2*>(ah + (size_t)(i * 256 + t) * 4) = pk;
    }
#pragma unroll
    for (int o = 16; o; o >>= 1) s += __shfl_xor_sync(0xffffffffu, s, o);

    __shared__ float ws[8];
    __shared__ float sdinv;
    if ((t & 31) == 0) ws[t >> 5] = s;
    __syncthreads();
    if (t < 32) {
        float v = (t < 8) ? ws[t] : 0.f;
#pragma unroll
        for (int o = 4; o; o >>= 1) v += __shfl_xor_sync(0xffffffffu, v, o);
        if (t == 0) {
            float d = rsqrtf(v + 1.0f);   // +1 self loop
            sdinv = d;
            g_dinv[row] = d;
        }
    }
    __syncthreads();
    const float d = sdinv;
    if (t < 32) {
        float4 xv = reinterpret_cast<const float4*>(x + (size_t)row * FEAT)[t];
        float4 yv;
        yv.x = d * xv.x; yv.y = d * xv.y; yv.z = d * xv.z; yv.w = d * xv.w;
        reinterpret_cast<float4*>(g_y + (size_t)row * FEAT)[t] = yv;
        uint2 pk = make_uint2(h2u(__floats2half2_rn(yv.x, yv.y)),
                              h2u(__floats2half2_rn(yv.z, yv.w)));
        *reinterpret_cast<uint2*>(g_yh + (size_t)row * FEAT + t * 4) = pk;
    }
}

// =================================================================
// Kernel 2: g_hp[split] = adjh[:, quarter] @ yh[quarter, :]  fp16 HMMA
// BM=128, BN=128, BK=32, 3-stage cp.async, split-K=4 -> 256 CTAs,
// occ 2 (NO aggressive reg cap — R10 showed occ-3 cap causes spills).
// 8 warps as 4(wm) x 2(wn); warp tile 32x64 = 2x4 wmma m16n16k16.
// =================================================================
constexpr int BM = 128;
constexpr int BK = 32;
constexpr int STAGES = 3;
constexpr int APITCH = 40;            // halfs (80B rows, LDSM conflict-free)
constexpr int BPITCH = FEAT + 8;      // 136 halfs (272B rows, conflict-free)
constexpr int SPLITK = 4;
constexpr int KPER = NROWS / SPLITK;  // 2048
constexpr int ITERS = KPER / BK;      // 64
constexpr int A_STAGE = BM * APITCH;  // 5120 halfs
constexpr int B_STAGE = BK * BPITCH;  // 4352 halfs
constexpr int SMEM_BYTES = STAGES * (A_STAGE + B_STAGE) * 2; // 56832

__global__ __launch_bounds__(256, 2) void k_gemm()
{
    extern __shared__ __half smem[];
    __half* As = smem;                         // [STAGES][BM][APITCH]
    __half* Bs = smem + STAGES * A_STAGE;      // [STAGES][BK][BPITCH]

    const int t = threadIdx.x;
    const int mtile = blockIdx.x >> 2;
    const int split = blockIdx.x & 3;
    const int rowBase = mtile * BM;
    const int kBase = split * KPER;

    auto load_stage = [&](int s, int kit) {
        const int k0 = kBase + kit * BK;
        // A tile: 128 rows x 32 halfs (64B/row) = 512 x 16B chunks, 2/thread
#pragma unroll
        for (int i = 0; i < 2; i++) {
            int lin = t + i * 256;
            int r = lin >> 2, c = (lin & 3) * 8;
            cp16s(&As[s * A_STAGE + r * APITCH + c],
                  g_adjh + (size_t)(rowBase + r) * NROWS + k0 + c);
        }
        // B tile: 32 rows x 128 halfs (256B/row) = 512 chunks, 2/thread
#pragma unroll
        for (int i = 0; i < 2; i++) {
            int lin = t + i * 256;
            int r = lin >> 4, c = (lin & 15) * 8;
            cp16s(&Bs[s * B_STAGE + r * BPITCH + c],
                  g_yh + (size_t)(k0 + r) * FEAT + c);
        }
    };

#pragma unroll
    for (int p = 0; p < STAGES - 1; p++) { load_stage(p, p); cp_commit(); }

    const int wid = t >> 5;
    const int wm = wid >> 1;   // 0..3  (32-row slab)
    const int wn = wid & 1;    // 0..1  (64-col slab)

    wmma::fragment<wmma::accumulator, 16, 16, 16, float> acc[2][4];
#pragma unroll
    for (int i = 0; i < 2; i++)
#pragma unroll
        for (int j = 0; j < 4; j++) wmma::fill_fragment(acc[i][j], 0.0f);

    for (int it = 0; it < ITERS; it++) {
        cp_wait<STAGES - 2>();
        __syncthreads();                  // stage it ready; all warps done with stage it-1
        int pf = it + STAGES - 1;
        if (pf < ITERS) load_stage(pf % STAGES, pf);
        cp_commit();

        const __half* A = &As[(it % STAGES) * A_STAGE];
        const __half* B = &Bs[(it % STAGES) * B_STAGE];
#pragma unroll
        for (int kk = 0; kk < BK / 16; kk++) {
            wmma::fragment<wmma::matrix_a, 16, 16, 16, __half, wmma::row_major> af[2];
#pragma unroll
            for (int i = 0; i < 2; i++)
                wmma::load_matrix_sync(af[i], A + (wm * 32 + i * 16) * APITCH + kk * 16, APITCH);
#pragma unroll
            for (int j = 0; j < 4; j++) {
                wmma::fragment<wmma::matrix_b, 16, 16, 16, __half, wmma::row_major> bf;
                wmma::load_matrix_sync(bf, B + (kk * 16) * BPITCH + wn * 64 + j * 16, BPITCH);
                wmma::mma_sync(acc[0][j], af[0], bf, acc[0][j]);
                wmma::mma_sync(acc[1][j], af[1], bf, acc[1][j]);
            }
        }
    }

#pragma unroll
    for (int i = 0; i < 2; i++)
#pragma unroll
        for (int j = 0; j < 4; j++)
            wmma::store_matrix_sync(
                &g_hp[split][(size_t)(rowBase + wm * 32 + i * 16) * FEAT + wn * 64 + j * 16],
                acc[i][j], FEAT, wmma::mem_row_major);
}

// =================================================================
// Kernel 3: h = dinv_i*((hp0+hp1+hp2+hp3) + y); z = h@W^T + b; L2-norm
// =================================================================
__global__ __launch_bounds__(256) void k_epilogue(
    const float* __restrict__ W, const float* __restrict__ bias,
    float* __restrict__ out)
{
    __shared__ float hs[64 * 132];
    const int t = threadIdx.x;
    const int row0 = blockIdx.x * 64;

#pragma unroll
    for (int i = 0; i < 8; i++) {
        int lin = t + i * 256;
        int r = lin >> 5, c = (lin & 31) * 4;
        size_t idx = (size_t)(row0 + r) * FEAT + c;
        float4 h0 = *reinterpret_cast<const float4*>(&g_hp[0][idx]);
        float4 h1 = *reinterpret_cast<const float4*>(&g_hp[1][idx]);
        float4 h2 = *reinterpret_cast<const float4*>(&g_hp[2][idx]);
        float4 h3 = *reinterpret_cast<const float4*>(&g_hp[3][idx]);
        float4 yv = *reinterpret_cast<const float4*>(&g_y[idx]);
        float d = g_dinv[row0 + r];
        float4 o;
        o.x = d * (((h0.x + h1.x) + (h2.x + h3.x)) + yv.x);
        o.y = d * (((h0.y + h1.y) + (h2.y + h3.y)) + yv.y);
        o.z = d * (((h0.z + h1.z) + (h2.z + h3.z)) + yv.z);
        o.w = d * (((h0.w + h1.w) + (h2.w + h3.w)) + yv.w);
        *reinterpret_cast<float4*>(&hs[r * 132 + c]) = o;
    }
    __syncthreads();

    const int wid = t >> 5, lane = t & 31;
    const int wm = wid >> 2, wn = wid & 3;

    wmma::fragment<wmma::accumulator, 16, 16, 8, float> acc[2][2];
#pragma unroll
    for (int i = 0; i < 2; i++)
#pragma unroll
        for (int j = 0; j < 2; j++) wmma::fill_fragment(acc[i][j], 0.0f);

    // z = h @ W^T : col_major view of row-major W, ld=FEAT  (tf32, tiny GEMM)
#pragma unroll
    for (int k0 = 0; k0 < FEAT; k0 += 8) {
        wmma::fragment<wmma::matrix_a, 16, 16, 8, wmma::precision::tf32, wmma::row_major> af[2];
        wmma::fragment<wmma::matrix_b, 16, 16, 8, wmma::precision::tf32, wmma::col_major> bf[2];
#pragma unroll
        for (int i = 0; i < 2; i++) {
            wmma::load_matrix_sync(af[i], &hs[(wm * 32 + i * 16) * 132 + k0], 132);
#pragma unroll
            for (int e = 0; e < af[i].num_elements; e++)
                af[i].x[e] = wmma::__float_to_tf32(af[i].x[e]);
        }
#pragma unroll
        for (int j = 0; j < 2; j++) {
            wmma::load_matrix_sync(bf[j], W + (size_t)(wn * 32 + j * 16) * FEAT + k0, FEAT);
#pragma unroll
            for (int e = 0; e < bf[j].num_elements; e++)
                bf[j].x[e] = wmma::__float_to_tf32(bf[j].x[e]);
        }
#pragma unroll
        for (int i = 0; i < 2; i++)
#pragma unroll
            for (int j = 0; j < 2; j++)
                wmma::mma_sync(acc[i][j], af[i], bf[j], acc[i][j]);
    }
    __syncthreads();

#pragma unroll
    for (int i = 0; i < 2; i++)
#pragma unroll
        for (int j = 0; j < 2; j++)
            wmma::store_matrix_sync(&hs[(wm * 32 + i * 16) * 132 + wn * 32 + j * 16],
                                    acc[i][j], 132, wmma::mem_row_major);
    __syncthreads();

    float4 bv = *reinterpret_cast<const float4*>(bias + lane * 4);
#pragma unroll
    for (int r8 = 0; r8 < 8; r8++) {
        int r = wid * 8 + r8;
        float4 z = *reinterpret_cast<float4*>(&hs[r * 132 + lane * 4]);
        z.x += bv.x; z.y += bv.y; z.z += bv.z; z.w += bv.w;
        float s = z.x * z.x + z.y * z.y + z.z * z.z + z.w * z.w;
#pragma unroll
        for (int o = 16; o; o >>= 1) s += __shfl_xor_sync(0xffffffffu, s, o);
        float inv = 1.0f / fmaxf(sqrtf(s), 1e-12f);
        float4 o4;
        o4.x = z.x * inv; o4.y = z.y * inv; o4.z = z.z * inv; o4.w = z.w * inv;
        *reinterpret_cast<float4*>(out + (size_t)(row0 + r) * FEAT + lane * 4) = o4;
    }
}

// =================================================================
// launch (graph-capturable, no allocs, default stream)
// inputs: x [8192,128], adj [8192,8192], W [128,128], b [128]
// =================================================================
extern "C" void kernel_launch(void* const* d_in, const int* in_sizes, int n_in,
                              void* d_out, int out_size)
{
    const float* x   = (const float*)d_in[0];
    const float* adj = (const float*)d_in[1];
    const float* W   = (const float*)d_in[2];
    const float* b   = (const float*)d_in[3];
    float* out = (float*)d_out;

    cudaStreamCaptureStatus cap = cudaStreamCaptureStatusNone;
    cudaStreamIsCapturing((cudaStream_t)0, &cap);
    if (cap == cudaStreamCaptureStatusNone) {
        cudaFuncSetAttribute(k_gemm, cudaFuncAttributeMaxDynamicSharedMemorySize,
                             SMEM_BYTES);
    }

    k_rowsum_y<<<NROWS, 256>>>(adj, x);
    k_gemm<<<(NROWS / BM) * SPLITK, 256, SMEM_BYTES>>>();
    k_epilogue<<<NROWS / 64, 256>>>(W, b, out);
}

// round 14
// speedup vs baseline: 1.2588x; 1.1248x over previous
#include <cuda_runtime.h>
#include <cuda_fp16.h>
#include <mma.h>
#include <cstdint>

using namespace nvcuda;

#define NROWS 8192
#define FEAT  128

// ---------------- scratch (no allocations allowed) ----------------
__device__ float  g_dinv[NROWS];
__device__ float  g_y [NROWS * FEAT];      // y = dinv*x, fp32 (k3 self-loop term)
__device__ __half g_yh[NROWS * FEAT];      // y in fp16 (GEMM B operand)
__device__ float  g_hp[2][NROWS * FEAT];   // split-K partials of adj @ y

// ================= helpers =================
__device__ __forceinline__ void cp16s(void* dst, const void* src) {
    uint32_t s = (uint32_t)__cvta_generic_to_shared(dst);
    asm volatile("cp.async.cg.shared.global [%0], [%1], 16;" :: "r"(s), "l"(src));
}
__device__ __forceinline__ void cp_commit() { asm volatile("cp.async.commit_group;"); }
template <int n> __device__ __forceinline__ void cp_wait() {
    asm volatile("cp.async.wait_group %0;" :: "n"(n));
}
__device__ __forceinline__ uint32_t h2u(__half2 h) {
    uint32_t u;
    memcpy(&u, &h, 4);
    return u;
}

// =================================================================
// Kernel 1: rowsum(adj)+1 -> dinv ; y = dinv*x ; yh = fp16(y)
// One block per row, 256 threads. (No adjh write — k2 converts inline.)
// =================================================================
__global__ __launch_bounds__(256) void k_rowsum_y(
    const float* __restrict__ adj, const float* __restrict__ x)
{
    const int row = blockIdx.x;
    const int t = threadIdx.x;
    const float4* a4 = reinterpret_cast<const float4*>(adj + (size_t)row * NROWS);

    float s = 0.f;
#pragma unroll
    for (int i = 0; i < 8; i++) {
        float4 v = a4[i * 256 + t];
        s += (v.x + v.y) + (v.z + v.w);
    }
#pragma unroll
    for (int o = 16; o; o >>= 1) s += __shfl_xor_sync(0xffffffffu, s, o);

    __shared__ float ws[8];
    __shared__ float sdinv;
    if ((t & 31) == 0) ws[t >> 5] = s;
    __syncthreads();
    if (t < 32) {
        float v = (t < 8) ? ws[t] : 0.f;
#pragma unroll
        for (int o = 4; o; o >>= 1) v += __shfl_xor_sync(0xffffffffu, v, o);
        if (t == 0) {
            float d = rsqrtf(v + 1.0f);   // +1 self loop
            sdinv = d;
            g_dinv[row] = d;
        }
    }
    __syncthreads();
    const float d = sdinv;
    if (t < 32) {
        float4 xv = reinterpret_cast<const float4*>(x + (size_t)row * FEAT)[t];
        float4 yv;
        yv.x = d * xv.x; yv.y = d * xv.y; yv.z = d * xv.z; yv.w = d * xv.w;
        reinterpret_cast<float4*>(g_y + (size_t)row * FEAT)[t] = yv;
        uint2 pk = make_uint2(h2u(__floats2half2_rn(yv.x, yv.y)),
                              h2u(__floats2half2_rn(yv.z, yv.w)));
        *reinterpret_cast<uint2*>(g_yh + (size_t)row * FEAT + t * 4) = pk;
    }
}

// =================================================================
// Kernel 2: g_hp[split] = fp16(adj[:, half]) @ yh[half, :]  fp16 HMMA
// A read as FP32 from adj with a 2-deep register pipeline:
//   LDG(it+2) -> regs -> cvt fp16 -> STS(it+1), 2-stage A smem.
// B via 4-stage cp.async from yh. BM=64, BK=32, split-K=2 (256 CTAs,
// occ 2, warp tile 32x32 — the proven no-spill config).
// =================================================================
constexpr int BM = 64;
constexpr int BK = 32;
constexpr int BSTAGES = 4;
constexpr int APITCH = 40;            // halfs (80B rows, LDSM conflict-free)
constexpr int BPITCH = FEAT + 8;      // 136 halfs (272B rows)
constexpr int SPLITK = 2;
constexpr int KPER = NROWS / SPLITK;  // 4096
constexpr int ITERS = KPER / BK;      // 128
constexpr int A_STAGE = BM * APITCH;  // 2560 halfs
constexpr int B_STAGE = BK * BPITCH;  // 4352 halfs

__global__ __launch_bounds__(256, 2) void k_gemm(const float* __restrict__ adj)
{
    __shared__ __half As[2][A_STAGE];        // 10 KB
    __shared__ __half Bs[BSTAGES][B_STAGE];  // 34 KB

    const int t = threadIdx.x;
    const int mtile = blockIdx.x >> 1;
    const int split = blockIdx.x & 1;
    const int rowBase = mtile * BM;
    const int kBase = split * KPER;

    // A addressing: tile 64 rows x 32 floats = 512 float4; 2 chunks/thread
    const int ar0 = t >> 3;              // rows 0..31  (chunk lin = t)
    const int ar1 = (t + 256) >> 3;      // rows 32..63 (chunk lin = t+256)
    const int ac = (t & 7) * 4;          // float col
    const float* aBase0 = adj + (size_t)(rowBase + ar0) * NROWS + kBase + ac;
    const float* aBase1 = adj + (size_t)(rowBase + ar1) * NROWS + kBase + ac;

    float4 ra0, ra1;                     // register A buffer (next iter's data)

    auto ldgA = [&](int kit) {
        ra0 = *reinterpret_cast<const float4*>(aBase0 + kit * BK);
        ra1 = *reinterpret_cast<const float4*>(aBase1 + kit * BK);
    };
    auto stsA = [&](int s) {
        uint2 p0 = make_uint2(h2u(__floats2half2_rn(ra0.x, ra0.y)),
                              h2u(__floats2half2_rn(ra0.z, ra0.w)));
        uint2 p1 = make_uint2(h2u(__floats2half2_rn(ra1.x, ra1.y)),
                              h2u(__floats2half2_rn(ra1.z, ra1.w)));
        *reinterpret_cast<uint2*>(&As[s][ar0 * APITCH + ac]) = p0;
        *reinterpret_cast<uint2*>(&As[s][ar1 * APITCH + ac]) = p1;
    };
    auto loadB = [&](int s, int kit) {
        const int k0 = kBase + kit * BK;
#pragma unroll
        for (int i = 0; i < 2; i++) {
            int lin = t + i * 256;
            int r = lin >> 4, c = (lin & 15) * 8;
            cp16s(&Bs[s][r * BPITCH + c], g_yh + (size_t)(k0 + r) * FEAT + c);
        }
    };

    // Prologue: A stages 0 in smem, stage 1 in regs; B stages 0..2 in flight.
    ldgA(0); stsA(0);
    ldgA(1);
    loadB(0, 0); cp_commit();
    loadB(1, 1); cp_commit();
    loadB(2, 2); cp_commit();

    const int wid = t >> 5;
    const int wm = wid >> 2;   // 0..1  (32-row slab)
    const int wn = wid & 3;    // 0..3  (32-col slab)

    wmma::fragment<wmma::accumulator, 16, 16, 16, float> acc[2][2];
#pragma unroll
    for (int i = 0; i < 2; i++)
#pragma unroll
        for (int j = 0; j < 2; j++) wmma::fill_fragment(acc[i][j], 0.0f);

    for (int it = 0; it < ITERS; it++) {
        cp_wait<2>();
        __syncthreads();   // As[it&1] + Bs[it%4] ready; all warps done with it-1

        if (it + 1 < ITERS) stsA((it + 1) & 1);   // regs -> smem for next iter
        if (it + 2 < ITERS) ldgA(it + 2);         // refill regs (2 iters ahead)
        if (it + 3 < ITERS) loadB((it + 3) % BSTAGES, it + 3);
        cp_commit();

        const __half* A = As[it & 1];
        const __half* B = Bs[it % BSTAGES];
#pragma unroll
        for (int kk = 0; kk < BK / 16; kk++) {
            wmma::fragment<wmma::matrix_a, 16, 16, 16, __half, wmma::row_major> af[2];
            wmma::fragment<wmma::matrix_b, 16, 16, 16, __half, wmma::row_major> bf[2];
#pragma unroll
            for (int i = 0; i < 2; i++)
                wmma::load_matrix_sync(af[i], A + (wm * 32 + i * 16) * APITCH + kk * 16, APITCH);
#pragma unroll
            for (int j = 0; j < 2; j++)
                wmma::load_matrix_sync(bf[j], B + (kk * 16) * BPITCH + wn * 32 + j * 16, BPITCH);
#pragma unroll
            for (int i = 0; i < 2; i++)
#pragma unroll
                for (int j = 0; j < 2; j++)
                    wmma::mma_sync(acc[i][j], af[i], bf[j], acc[i][j]);
        }
    }

#pragma unroll
    for (int i = 0; i < 2; i++)
#pragma unroll
        for (int j = 0; j < 2; j++)
            wmma::store_matrix_sync(
                &g_hp[split][(size_t)(rowBase + wm * 32 + i * 16) * FEAT + wn * 32 + j * 16],
                acc[i][j], FEAT, wmma::mem_row_major);
}

// =================================================================
// Kernel 3: h = dinv_i*((hp0+hp1) + y); z = h@W^T + b; L2-normalize
// =================================================================
__global__ __launch_bounds__(256) void k_epilogue(
    const float* __restrict__ W, const float* __restrict__ bias,
    float* __restrict__ out)
{
    __shared__ float hs[64 * 132];
    const int t = threadIdx.x;
    const int row0 = blockIdx.x * 64;

#pragma unroll
    for (int i = 0; i < 8; i++) {
        int lin = t + i * 256;
        int r = lin >> 5, c = (lin & 31) * 4;
        size_t idx = (size_t)(row0 + r) * FEAT + c;
        float4 h0 = *reinterpret_cast<const float4*>(&g_hp[0][idx]);
        float4 h1 = *reinterpret_cast<const float4*>(&g_hp[1][idx]);
        float4 yv = *reinterpret_cast<const float4*>(&g_y[idx]);
        float d = g_dinv[row0 + r];
        float4 o;
        o.x = d * ((h0.x + h1.x) + yv.x);
        o.y = d * ((h0.y + h1.y) + yv.y);
        o.z = d * ((h0.z + h1.z) + yv.z);
        o.w = d * ((h0.w + h1.w) + yv.w);
        *reinterpret_cast<float4*>(&hs[r * 132 + c]) = o;
    }
    __syncthreads();

    const int wid = t >> 5, lane = t & 31;
    const int wm = wid >> 2, wn = wid & 3;

    wmma::fragment<wmma::accumulator, 16, 16, 8, float> acc[2][2];
#pragma unroll
    for (int i = 0; i < 2; i++)
#pragma unroll
        for (int j = 0; j < 2; j++) wmma::fill_fragment(acc[i][j], 0.0f);

    // z = h @ W^T : col_major view of row-major W, ld=FEAT  (tf32, tiny GEMM)
#pragma unroll
    for (int k0 = 0; k0 < FEAT; k0 += 8) {
        wmma::fragment<wmma::matrix_a, 16, 16, 8, wmma::precision::tf32, wmma::row_major> af[2];
        wmma::fragment<wmma::matrix_b, 16, 16, 8, wmma::precision::tf32, wmma::col_major> bf[2];
#pragma unroll
        for (int i = 0; i < 2; i++) {
            wmma::load_matrix_sync(af[i], &hs[(wm * 32 + i * 16) * 132 + k0], 132);
#pragma unroll
            for (int e = 0; e < af[i].num_elements; e++)
                af[i].x[e] = wmma::__float_to_tf32(af[i].x[e]);
        }
#pragma unroll
        for (int j = 0; j < 2; j++) {
            wmma::load_matrix_sync(bf[j], W + (size_t)(wn * 32 + j * 16) * FEAT + k0, FEAT);
#pragma unroll
            for (int e = 0; e < bf[j].num_elements; e++)
                bf[j].x[e] = wmma::__float_to_tf32(bf[j].x[e]);
        }
#pragma unroll
        for (int i = 0; i < 2; i++)
#pragma unroll
            for (int j = 0; j < 2; j++)
                wmma::mma_sync(acc[i][j], af[i], bf[j], acc[i][j]);
    }
    __syncthreads();

#pragma unroll
    for (int i = 0; i < 2; i++)
#pragma unroll
        for (int j = 0; j < 2; j++)
            wmma::store_matrix_sync(&hs[(wm * 32 + i * 16) * 132 + wn * 32 + j * 16],
                                    acc[i][j], 132, wmma::mem_row_major);
    __syncthreads();

    float4 bv = *reinterpret_cast<const float4*>(bias + lane * 4);
#pragma unroll
    for (int r8 = 0; r8 < 8; r8++) {
        int r = wid * 8 + r8;
        float4 z = *reinterpret_cast<float4*>(&hs[r * 132 + lane * 4]);
        z.x += bv.x; z.y += bv.y; z.z += bv.z; z.w += bv.w;
        float s = z.x * z.x + z.y * z.y + z.z * z.z + z.w * z.w;
#pragma unroll
        for (int o = 16; o; o >>= 1) s += __shfl_xor_sync(0xffffffffu, s, o);
        float inv = 1.0f / fmaxf(sqrtf(s), 1e-12f);
        float4 o4;
        o4.x = z.x * inv; o4.y = z.y * inv; o4.z = z.z * inv; o4.w = z.w * inv;
        *reinterpret_cast<float4*>(out + (size_t)(row0 + r) * FEAT + lane * 4) = o4;
    }
}

// =================================================================
// launch (graph-capturable, no allocs, default stream)
// inputs: x [8192,128], adj [8192,8192], W [128,128], b [128]
// =================================================================
extern "C" void kernel_launch(void* const* d_in, const int* in_sizes, int n_in,
                              void* d_out, int out_size)
{
    const float* x   = (const float*)d_in[0];
    const float* adj = (const float*)d_in[1];
    const float* W   = (const float*)d_in[2];
    const float* b   = (const float*)d_in[3];
    float* out = (float*)d_out;

    k_rowsum_y<<<NROWS, 256>>>(adj, x);
    k_gemm<<<(NROWS / BM) * SPLITK, 256>>>(adj);
    k_epilogue<<<NROWS / 64, 256>>>(W, b, out);
}

// round 15
// speedup vs baseline: 1.3797x; 1.0960x over previous
#include <cuda_runtime.h>
#include <cuda_fp16.h>
#include <mma.h>
#include <cstdint>

using namespace nvcuda;

#define NROWS 8192
#define FEAT  128

// ---------------- scratch (no allocations allowed) ----------------
__device__ float  g_dinv[NROWS];
__device__ float  g_y [NROWS * FEAT];          // y = dinv*x, fp32 (k3 self-loop term)
__device__ __half g_yh[NROWS * FEAT];          // y in fp16 (GEMM B operand)
__device__ __half g_adjh[(size_t)NROWS * NROWS];  // adj in fp16 (GEMM A operand)
__device__ float  g_hp[2][NROWS * FEAT];       // split-K partials of adj @ y

// ================= helpers =================
__device__ __forceinline__ void cp16s(void* dst, const void* src) {
    uint32_t s = (uint32_t)__cvta_generic_to_shared(dst);
    asm volatile("cp.async.cg.shared.global [%0], [%1], 16;" :: "r"(s), "l"(src));
}
__device__ __forceinline__ void cp_commit() { asm volatile("cp.async.commit_group;"); }
template <int n> __device__ __forceinline__ void cp_wait() {
    asm volatile("cp.async.wait_group %0;" :: "n"(n));
}
__device__ __forceinline__ uint32_t h2u(__half2 h) {
    uint32_t u;
    memcpy(&u, &h, 4);
    return u;
}

// =================================================================
// Kernel 1: rowsum(adj)+1 -> dinv ; adjh = fp16(adj) ; y = dinv*x ;
//           yh = fp16(y).  One block per row, 256 threads.
// =================================================================
__global__ __launch_bounds__(256) void k_rowsum_y(
    const float* __restrict__ adj, const float* __restrict__ x)
{
    const int row = blockIdx.x;
    const int t = threadIdx.x;
    const float4* a4 = reinterpret_cast<const float4*>(adj + (size_t)row * NROWS);
    __half* ah = g_adjh + (size_t)row * NROWS;

    float s = 0.f;
#pragma unroll
    for (int i = 0; i < 8; i++) {
        float4 v = a4[i * 256 + t];
        s += (v.x + v.y) + (v.z + v.w);
        uint2 pk = make_uint2(h2u(__floats2half2_rn(v.x, v.y)),
                              h2u(__floats2half2_rn(v.z, v.w)));
        *reinterpret_cast<uint2*>(ah + (size_t)(i * 256 + t) * 4) = pk;
    }
#pragma unroll
    for (int o = 16; o; o >>= 1) s += __shfl_xor_sync(0xffffffffu, s, o);

    __shared__ float ws[8];
    __shared__ float sdinv;
    if ((t & 31) == 0) ws[t >> 5] = s;
    __syncthreads();
    if (t < 32) {
        float v = (t < 8) ? ws[t] : 0.f;
#pragma unroll
        for (int o = 4; o; o >>= 1) v += __shfl_xor_sync(0xffffffffu, v, o);
        if (t == 0) {
            float d = rsqrtf(v + 1.0f);   // +1 self loop
            sdinv = d;
            g_dinv[row] = d;
        }
    }
    __syncthreads();
    const float d = sdinv;
    if (t < 32) {
        float4 xv = reinterpret_cast<const float4*>(x + (size_t)row * FEAT)[t];
        float4 yv;
        yv.x = d * xv.x; yv.y = d * xv.y; yv.z = d * xv.z; yv.w = d * xv.w;
        reinterpret_cast<float4*>(g_y + (size_t)row * FEAT)[t] = yv;
        uint2 pk = make_uint2(h2u(__floats2half2_rn(yv.x, yv.y)),
                              h2u(__floats2half2_rn(yv.z, yv.w)));
        *reinterpret_cast<uint2*>(g_yh + (size_t)row * FEAT + t * 4) = pk;
    }
}

// =================================================================
// Kernel 2: g_hp[split] = adjh[:, half] @ yh[half, :]   fp16 HMMA
// BM=64, BN=128, BK=64 (double work per barrier vs R9), 3-stage
// cp.async, split-K=2 -> 256 CTAs, occ 2, warp tile 32x32 (no-spill).
// =================================================================
constexpr int BM = 64;
constexpr int BK = 64;
constexpr int STAGES = 3;
constexpr int APITCH = BK + 8;        // 72 halfs (144B rows, LDSM conflict-free)
constexpr int BPITCH = FEAT + 8;      // 136 halfs (272B rows)
constexpr int SPLITK = 2;
constexpr int KPER = NROWS / SPLITK;  // 4096
constexpr int ITERS = KPER / BK;      // 64
constexpr int A_STAGE = BM * APITCH;  // 4608 halfs
constexpr int B_STAGE = BK * BPITCH;  // 8704 halfs
constexpr int SMEM_BYTES = STAGES * (A_STAGE + B_STAGE) * 2; // 79872

__global__ __launch_bounds__(256, 2) void k_gemm()
{
    extern __shared__ __half smem[];
    __half* As = smem;                         // [STAGES][BM][APITCH]
    __half* Bs = smem + STAGES * A_STAGE;      // [STAGES][BK][BPITCH]

    const int t = threadIdx.x;
    const int mtile = blockIdx.x >> 1;
    const int split = blockIdx.x & 1;
    const int rowBase = mtile * BM;
    const int kBase = split * KPER;

    auto load_stage = [&](int s, int kit) {
        const int k0 = kBase + kit * BK;
        // A tile: 64 rows x 64 halfs (128B/row) = 512 x 16B chunks, 2/thread
#pragma unroll
        for (int i = 0; i < 2; i++) {
            int lin = t + i * 256;
            int r = lin >> 3, c = (lin & 7) * 8;
            cp16s(&As[s * A_STAGE + r * APITCH + c],
                  g_adjh + (size_t)(rowBase + r) * NROWS + k0 + c);
        }
        // B tile: 64 rows x 128 halfs (256B/row) = 1024 chunks, 4/thread
#pragma unroll
        for (int i = 0; i < 4; i++) {
            int lin = t + i * 256;
            int r = lin >> 4, c = (lin & 15) * 8;
            cp16s(&Bs[s * B_STAGE + r * BPITCH + c],
                  g_yh + (size_t)(k0 + r) * FEAT + c);
        }
    };

#pragma unroll
    for (int p = 0; p < STAGES - 1; p++) { load_stage(p, p); cp_commit(); }

    const int wid = t >> 5;
    const int wm = wid >> 2;   // 0..1  (32-row slab)
    const int wn = wid & 3;    // 0..3  (32-col slab)

    wmma::fragment<wmma::accumulator, 16, 16, 16, float> acc[2][2];
#pragma unroll
    for (int i = 0; i < 2; i++)
#pragma unroll
        for (int j = 0; j < 2; j++) wmma::fill_fragment(acc[i][j], 0.0f);

    for (int it = 0; it < ITERS; it++) {
        cp_wait<STAGES - 2>();
        __syncthreads();                  // stage it ready; all warps done with stage it-1
        int pf = it + STAGES - 1;
        if (pf < ITERS) load_stage(pf % STAGES, pf);
        cp_commit();

        const __half* A = &As[(it % STAGES) * A_STAGE];
        const __half* B = &Bs[(it % STAGES) * B_STAGE];
#pragma unroll
        for (int kk = 0; kk < BK / 16; kk++) {
            wmma::fragment<wmma::matrix_a, 16, 16, 16, __half, wmma::row_major> af[2];
            wmma::fragment<wmma::matrix_b, 16, 16, 16, __half, wmma::row_major> bf[2];
#pragma unroll
            for (int i = 0; i < 2; i++)
                wmma::load_matrix_sync(af[i], A + (wm * 32 + i * 16) * APITCH + kk * 16, APITCH);
#pragma unroll
            for (int j = 0; j < 2; j++)
                wmma::load_matrix_sync(bf[j], B + (kk * 16) * BPITCH + wn * 32 + j * 16, BPITCH);
#pragma unroll
            for (int i = 0; i < 2; i++)
#pragma unroll
                for (int j = 0; j < 2; j++)
                    wmma::mma_sync(acc[i][j], af[i], bf[j], acc[i][j]);
        }
    }

#pragma unroll
    for (int i = 0; i < 2; i++)
#pragma unroll
        for (int j = 0; j < 2; j++)
            wmma::store_matrix_sync(
                &g_hp[split][(size_t)(rowBase + wm * 32 + i * 16) * FEAT + wn * 32 + j * 16],
                acc[i][j], FEAT, wmma::mem_row_major);
}

// =================================================================
// Kernel 3: h = dinv_i*((hp0+hp1) + y); z = h@W^T + b; L2-normalize
// =================================================================
__global__ __launch_bounds__(256) void k_epilogue(
    const float* __restrict__ W, const float* __restrict__ bias,
    float* __restrict__ out)
{
    __shared__ float hs[64 * 132];
    const int t = threadIdx.x;
    const int row0 = blockIdx.x * 64;

#pragma unroll
    for (int i = 0; i < 8; i++) {
        int lin = t + i * 256;
        int r = lin >> 5, c = (lin & 31) * 4;
        size_t idx = (size_t)(row0 + r) * FEAT + c;
        float4 h0 = *reinterpret_cast<const float4*>(&g_hp[0][idx]);
        float4 h1 = *reinterpret_cast<const float4*>(&g_hp[1][idx]);
        float4 yv = *reinterpret_cast<const float4*>(&g_y[idx]);
        float d = g_dinv[row0 + r];
        float4 o;
        o.x = d * ((h0.x + h1.x) + yv.x);
        o.y = d * ((h0.y + h1.y) + yv.y);
        o.z = d * ((h0.z + h1.z) + yv.z);
        o.w = d * ((h0.w + h1.w) + yv.w);
        *reinterpret_cast<float4*>(&hs[r * 132 + c]) = o;
    }
    __syncthreads();

    const int wid = t >> 5, lane = t & 31;
    const int wm = wid >> 2, wn = wid & 3;

    wmma::fragment<wmma::accumulator, 16, 16, 8, float> acc[2][2];
#pragma unroll
    for (int i = 0; i < 2; i++)
#pragma unroll
        for (int j = 0; j < 2; j++) wmma::fill_fragment(acc[i][j], 0.0f);

    // z = h @ W^T : col_major view of row-major W, ld=FEAT  (tf32, tiny GEMM)
#pragma unroll
    for (int k0 = 0; k0 < FEAT; k0 += 8) {
        wmma::fragment<wmma::matrix_a, 16, 16, 8, wmma::precision::tf32, wmma::row_major> af[2];
        wmma::fragment<wmma::matrix_b, 16, 16, 8, wmma::precision::tf32, wmma::col_major> bf[2];
#pragma unroll
        for (int i = 0; i < 2; i++) {
            wmma::load_matrix_sync(af[i], &hs[(wm * 32 + i * 16) * 132 + k0], 132);
#pragma unroll
            for (int e = 0; e < af[i].num_elements; e++)
                af[i].x[e] = wmma::__float_to_tf32(af[i].x[e]);
        }
#pragma unroll
        for (int j = 0; j < 2; j++) {
            wmma::load_matrix_sync(bf[j], W + (size_t)(wn * 32 + j * 16) * FEAT + k0, FEAT);
#pragma unroll
            for (int e = 0; e < bf[j].num_elements; e++)
                bf[j].x[e] = wmma::__float_to_tf32(bf[j].x[e]);
        }
#pragma unroll
        for (int i = 0; i < 2; i++)
#pragma unroll
            for (int j = 0; j < 2; j++)
                wmma::mma_sync(acc[i][j], af[i], bf[j], acc[i][j]);
    }
    __syncthreads();

#pragma unroll
    for (int i = 0; i < 2; i++)
#pragma unroll
        for (int j = 0; j < 2; j++)
            wmma::store_matrix_sync(&hs[(wm * 32 + i * 16) * 132 + wn * 32 + j * 16],
                                    acc[i][j], 132, wmma::mem_row_major);
    __syncthreads();

    float4 bv = *reinterpret_cast<const float4*>(bias + lane * 4);
#pragma unroll
    for (int r8 = 0; r8 < 8; r8++) {
        int r = wid * 8 + r8;
        float4 z = *reinterpret_cast<float4*>(&hs[r * 132 + lane * 4]);
        z.x += bv.x; z.y += bv.y; z.z += bv.z; z.w += bv.w;
        float s = z.x * z.x + z.y * z.y + z.z * z.z + z.w * z.w;
#pragma unroll
        for (int o = 16; o; o >>= 1) s += __shfl_xor_sync(0xffffffffu, s, o);
        float inv = 1.0f / fmaxf(sqrtf(s), 1e-12f);
        float4 o4;
        o4.x = z.x * inv; o4.y = z.y * inv; o4.z = z.z * inv; o4.w = z.w * inv;
        *reinterpret_cast<float4*>(out + (size_t)(row0 + r) * FEAT + lane * 4) = o4;
    }
}

// =================================================================
// launch (graph-capturable, no allocs, default stream)
// inputs: x [8192,128], adj [8192,8192], W [128,128], b [128]
// =================================================================
extern "C" void kernel_launch(void* const* d_in, const int* in_sizes, int n_in,
                              void* d_out, int out_size)
{
    const float* x   = (const float*)d_in[0];
    const float* adj = (const float*)d_in[1];
    const float* W   = (const float*)d_in[2];
    const float* b   = (const float*)d_in[3];
    float* out = (float*)d_out;

    cudaStreamCaptureStatus cap = cudaStreamCaptureStatusNone;
    cudaStreamIsCapturing((cudaStream_t)0, &cap);
    if (cap == cudaStreamCaptureStatusNone) {
        cudaFuncSetAttribute(k_gemm, cudaFuncAttributeMaxDynamicSharedMemorySize,
                             SMEM_BYTES);
    }

    k_rowsum_y<<<NROWS, 256>>>(adj, x);
    k_gemm<<<(NROWS / BM) * SPLITK, 256, SMEM_BYTES>>>();
    k_epilogue<<<NROWS / 64, 256>>>(W, b, out);
}

// round 17
// speedup vs baseline: 1.4279x; 1.0350x over previous
#include <cuda_runtime.h>
#include <cuda_fp16.h>
#include <mma.h>
#include <cstdint>

using namespace nvcuda;

#define NROWS 8192
#define FEAT  128

// ---------------- scratch (no allocations allowed) ----------------
__device__ float  g_dinv[NROWS];
__device__ float  g_y [NROWS * FEAT];          // y = dinv*x, fp32 (k3 self-loop term)
__device__ __half g_yh[NROWS * FEAT];          // y in fp16 (GEMM B operand)
__device__ __half g_adjh[(size_t)NROWS * NROWS];  // adj in fp16 (GEMM A operand)
__device__ float  g_hp[2][NROWS * FEAT];       // split-K partials of adj @ y

// ================= helpers =================
__device__ __forceinline__ void cp16s(void* dst, const void* src) {
    uint32_t s = (uint32_t)__cvta_generic_to_shared(dst);
    asm volatile("cp.async.cg.shared.global [%0], [%1], 16;" :: "r"(s), "l"(src));
}
__device__ __forceinline__ void cp_commit() { asm volatile("cp.async.commit_group;"); }
template <int n> __device__ __forceinline__ void cp_wait() {
    asm volatile("cp.async.wait_group %0;" :: "n"(n));
}
__device__ __forceinline__ uint32_t h2u(__half2 h) {
    uint32_t u;
    memcpy(&u, &h, 4);
    return u;
}
#define BAR_SYNC(id, cnt)   asm volatile("bar.sync %0, %1;"   :: "r"(id), "r"(cnt) : "memory")
#define BAR_ARRIVE(id, cnt) asm volatile("bar.arrive %0, %1;" :: "r"(id), "r"(cnt) : "memory")

// =================================================================
// Kernel 1: rowsum(adj)+1 -> dinv ; adjh = fp16(adj) ; y = dinv*x ;
//           yh = fp16(y).  One block per row, 256 threads.
// =================================================================
__global__ __launch_bounds__(256) void k_rowsum_y(
    const float* __restrict__ adj, const float* __restrict__ x)
{
    const int row = blockIdx.x;
    const int t = threadIdx.x;
    const float4* a4 = reinterpret_cast<const float4*>(adj + (size_t)row * NROWS);
    __half* ah = g_adjh + (size_t)row * NROWS;

    float s = 0.f;
#pragma unroll
    for (int i = 0; i < 8; i++) {
        float4 v = a4[i * 256 + t];
        s += (v.x + v.y) + (v.z + v.w);
        uint2 pk = make_uint2(h2u(__floats2half2_rn(v.x, v.y)),
                              h2u(__floats2half2_rn(v.z, v.w)));
        *reinterpret_cast<uint2*>(ah + (size_t)(i * 256 + t) * 4) = pk;
    }
#pragma unroll
    for (int o = 16; o; o >>= 1) s += __shfl_xor_sync(0xffffffffu, s, o);

    __shared__ float ws[8];
    __shared__ float sdinv;
    if ((t & 31) == 0) ws[t >> 5] = s;
    __syncthreads();
    if (t < 32) {
        float v = (t < 8) ? ws[t] : 0.f;
#pragma unroll
        for (int o = 4; o; o >>= 1) v += __shfl_xor_sync(0xffffffffu, v, o);
        if (t == 0) {
            float d = rsqrtf(v + 1.0f);   // +1 self loop
            sdinv = d;
            g_dinv[row] = d;
        }
    }
    __syncthreads();
    const float d = sdinv;
    if (t < 32) {
        float4 xv = reinterpret_cast<const float4*>(x + (size_t)row * FEAT)[t];
        float4 yv;
        yv.x = d * xv.x; yv.y = d * xv.y; yv.z = d * xv.z; yv.w = d * xv.w;
        reinterpret_cast<float4*>(g_y + (size_t)row * FEAT)[t] = yv;
        uint2 pk = make_uint2(h2u(__floats2half2_rn(yv.x, yv.y)),
                              h2u(__floats2half2_rn(yv.z, yv.w)));
        *reinterpret_cast<uint2*>(g_yh + (size_t)row * FEAT + t * 4) = pk;
    }
}

// =================================================================
// Kernel 2: g_hp[split] = adjh[:, half] @ yh[half, :]   fp16 HMMA
// WARP-SPECIALIZED: 8 compute warps (wid 0-7, 32x32 wmma tiles) +
// 2 producer warps (wid 8-9) that own ALL cp.async traffic.
// 4-stage pipeline, named-barrier handoff:
//   producer: sync(FREE_s) -> cp.async -> commit -> wait<2> -> arrive(READY_{s-2})
//   consumer: sync(READY_s) -> LDSM/HMMA -> arrive(FREE_s)
// BM=64, BN=128, BK=32, split-K=2 -> 256 CTAs, 2 CTAs/SM.
// =================================================================
constexpr int BM = 64;
constexpr int BK = 32;
constexpr int S = 4;                  // stages
constexpr int APITCH = 40;            // halfs (80B rows, LDSM conflict-free)
constexpr int BPITCH = FEAT + 8;      // 136 halfs (272B rows)
constexpr int SPLITK = 2;
constexpr int KPER = NROWS / SPLITK;  // 4096
constexpr int ITERS = KPER / BK;      // 128
constexpr int A_STAGE = BM * APITCH;  // 2560 halfs
constexpr int B_STAGE = BK * BPITCH;  // 4352 halfs
constexpr int SMEM_BYTES = S * (A_STAGE + B_STAGE) * 2;   // 55296
constexpr int NTHREADS = 320;         // 8 compute + 2 producer warps
// barrier ids: FREE_s = 1+s, READY_s = 5+s

__global__ __launch_bounds__(NTHREADS, 2) void k_gemm()
{
    extern __shared__ __half smem[];
    __half* As = smem;                         // [S][BM][APITCH]
    __half* Bs = smem + S * A_STAGE;           // [S][BK][BPITCH]

    const int t = threadIdx.x;
    const int wid = t >> 5;
    const int mtile = blockIdx.x >> 1;
    const int split = blockIdx.x & 1;
    const int rowBase = mtile * BM;
    const int kBase = split * KPER;

    if (wid >= 8) {
        // ---------------- PRODUCER (64 threads) ----------------
        const int tp = t - 256;
        for (int kit = 0; kit < ITERS; kit++) {
            const int s = kit & (S - 1);
            if (kit >= S) BAR_SYNC(1 + s, NTHREADS);         // wait stage free
            const int k0 = kBase + kit * BK;
            // A tile: 64 rows x 32 halfs = 256 x 16B chunks, 4/thread
#pragma unroll
            for (int i = 0; i < 4; i++) {
                int lin = tp + i * 64;
                int r = lin >> 2, c = (lin & 3) * 8;
                cp16s(&As[s * A_STAGE + r * APITCH + c],
                      g_adjh + (size_t)(rowBase + r) * NROWS + k0 + c);
            }
            // B tile: 32 rows x 128 halfs = 512 chunks, 8/thread
#pragma unroll
            for (int i = 0; i < 8; i++) {
                int lin = tp + i * 64;
                int r = lin >> 4, c = (lin & 15) * 8;
                cp16s(&Bs[s * B_STAGE + r * BPITCH + c],
                      g_yh + (size_t)(k0 + r) * FEAT + c);
            }
            cp_commit();
            if (kit >= 2) {                                  // group kit-2 done
                cp_wait<2>();
                BAR_ARRIVE(5 + ((kit - 2) & (S - 1)), NTHREADS);
            }
        }
        cp_wait<0>();                                        // flush tail stages
        BAR_ARRIVE(5 + ((ITERS - 2) & (S - 1)), NTHREADS);
        BAR_ARRIVE(5 + ((ITERS - 1) & (S - 1)), NTHREADS);
    } else {
        // ---------------- CONSUMER (256 threads, 8 warps) ----------------
        const int wm = wid >> 2;   // 0..1  (32-row slab)
        const int wn = wid & 3;    // 0..3  (32-col slab)

        wmma::fragment<wmma::accumulator, 16, 16, 16, float> acc[2][2];
#pragma unroll
        for (int i = 0; i < 2; i++)
#pragma unroll
            for (int j = 0; j < 2; j++) wmma::fill_fragment(acc[i][j], 0.0f);

        for (int it = 0; it < ITERS; it++) {
            const int s = it & (S - 1);
            BAR_SYNC(5 + s, NTHREADS);                       // wait stage ready

            const __half* A = &As[s * A_STAGE];
            const __half* B = &Bs[s * B_STAGE];
#pragma unroll
            for (int kk = 0; kk < BK / 16; kk++) {
                wmma::fragment<wmma::matrix_a, 16, 16, 16, __half, wmma::row_major> af[2];
                wmma::fragment<wmma::matrix_b, 16, 16, 16, __half, wmma::row_major> bf[2];
#pragma unroll
                for (int i = 0; i < 2; i++)
                    wmma::load_matrix_sync(af[i], A + (wm * 32 + i * 16) * APITCH + kk * 16, APITCH);
#pragma unroll
                for (int j = 0; j < 2; j++)
                    wmma::load_matrix_sync(bf[j], B + (kk * 16) * BPITCH + wn * 32 + j * 16, BPITCH);
#pragma unroll
                for (int i = 0; i < 2; i++)
#pragma unroll
                    for (int j = 0; j < 2; j++)
                        wmma::mma_sync(acc[i][j], af[i], bf[j], acc[i][j]);
            }
            BAR_ARRIVE(1 + s, NTHREADS);                     // stage free
        }

#pragma unroll
        for (int i = 0; i < 2; i++)
#pragma unroll
            for (int j = 0; j < 2; j++)
                wmma::store_matrix_sync(
                    &g_hp[split][(size_t)(rowBase + wm * 32 + i * 16) * FEAT + wn * 32 + j * 16],
                    acc[i][j], FEAT, wmma::mem_row_major);
    }
}

// =================================================================
// Kernel 3: h = dinv_i*((hp0+hp1) + y); z = h@W^T + b; L2-normalize
// =================================================================
__global__ __launch_bounds__(256) void k_epilogue(
    const float* __restrict__ W, const float* __restrict__ bias,
    float* __restrict__ out)
{
    __shared__ float hs[64 * 132];
    const int t = threadIdx.x;
    const int row0 = blockIdx.x * 64;

#pragma unroll
    for (int i = 0; i < 8; i++) {
        int lin = t + i * 256;
        int r = lin >> 5, c = (lin & 31) * 4;
        size_t idx = (size_t)(row0 + r) * FEAT + c;
        float4 h0 = *reinterpret_cast<const float4*>(&g_hp[0][idx]);
        float4 h1 = *reinterpret_cast<const float4*>(&g_hp[1][idx]);
        float4 yv = *reinterpret_cast<const float4*>(&g_y[idx]);
        float d = g_dinv[row0 + r];
        float4 o;
        o.x = d * ((h0.x + h1.x) + yv.x);
        o.y = d * ((h0.y + h1.y) + yv.y);
        o.z = d * ((h0.z + h1.z) + yv.z);
        o.w = d * ((h0.w + h1.w) + yv.w);
        *reinterpret_cast<float4*>(&hs[r * 132 + c]) = o;
    }
    __syncthreads();

    const int wid = t >> 5, lane = t & 31;
    const int wm = wid >> 2, wn = wid & 3;

    wmma::fragment<wmma::accumulator, 16, 16, 8, float> acc[2][2];
#pragma unroll
    for (int i = 0; i < 2; i++)
#pragma unroll
        for (int j = 0; j < 2; j++) wmma::fill_fragment(acc[i][j], 0.0f);

    // z = h @ W^T : col_major view of row-major W, ld=FEAT  (tf32, tiny GEMM)
#pragma unroll
    for (int k0 = 0; k0 < FEAT; k0 += 8) {
        wmma::fragment<wmma::matrix_a, 16, 16, 8, wmma::precision::tf32, wmma::row_major> af[2];
        wmma::fragment<wmma::matrix_b, 16, 16, 8, wmma::precision::tf32, wmma::col_major> bf[2];
#pragma unroll
        for (int i = 0; i < 2; i++) {
            wmma::load_matrix_sync(af[i], &hs[(wm * 32 + i * 16) * 132 + k0], 132);
#pragma unroll
            for (int e = 0; e < af[i].num_elements; e++)
                af[i].x[e] = wmma::__float_to_tf32(af[i].x[e]);
        }
#pragma unroll
        for (int j = 0; j < 2; j++) {
            wmma::load_matrix_sync(bf[j], W + (size_t)(wn * 32 + j * 16) * FEAT + k0, FEAT);
#pragma unroll
            for (int e = 0; e < bf[j].num_elements; e++)
                bf[j].x[e] = wmma::__float_to_tf32(bf[j].x[e]);
        }
#pragma unroll
        for (int i = 0; i < 2; i++)
#pragma unroll
            for (int j = 0; j < 2; j++)
                wmma::mma_sync(acc[i][j], af[i], bf[j], acc[i][j]);
    }
    __syncthreads();

#pragma unroll
    for (int i = 0; i < 2; i++)
#pragma unroll
        for (int j = 0; j < 2; j++)
            wmma::store_matrix_sync(&hs[(wm * 32 + i * 16) * 132 + wn * 32 + j * 16],
                                    acc[i][j], 132, wmma::mem_row_major);
    __syncthreads();

    float4 bv = *reinterpret_cast<const float4*>(bias + lane * 4);
#pragma unroll
    for (int r8 = 0; r8 < 8; r8++) {
        int r = wid * 8 + r8;
        float4 z = *reinterpret_cast<float4*>(&hs[r * 132 + lane * 4]);
        z.x += bv.x; z.y += bv.y; z.z += bv.z; z.w += bv.w;
        float s = z.x * z.x + z.y * z.y + z.z * z.z + z.w * z.w;
#pragma unroll
        for (int o = 16; o; o >>= 1) s += __shfl_xor_sync(0xffffffffu, s, o);
        float inv = 1.0f / fmaxf(sqrtf(s), 1e-12f);
        float4 o4;
        o4.x = z.x * inv; o4.y = z.y * inv; o4.z = z.z * inv; o4.w = z.w * inv;
        *reinterpret_cast<float4*>(out + (size_t)(row0 + r) * FEAT + lane * 4) = o4;
    }
}

// =================================================================
// launch (graph-capturable, no allocs, default stream)
// inputs: x [8192,128], adj [8192,8192], W [128,128], b [128]
// =================================================================
extern "C" void kernel_launch(void* const* d_in, const int* in_sizes, int n_in,
                              void* d_out, int out_size)
{
    const float* x   = (const float*)d_in[0];
    const float* adj = (const float*)d_in[1];
    const float* W   = (const float*)d_in[2];
    const float* b   = (const float*)d_in[3];
    float* out = (float*)d_out;

    cudaStreamCaptureStatus cap = cudaStreamCaptureStatusNone;
    cudaStreamIsCapturing((cudaStream_t)0, &cap);
    if (cap == cudaStreamCaptureStatusNone) {
        cudaFuncSetAttribute(k_gemm, cudaFuncAttributeMaxDynamicSharedMemorySize,
                             SMEM_BYTES);
    }

    k_rowsum_y<<<NROWS, 256>>>(adj, x);
    k_gemm<<<(NROWS / BM) * SPLITK, NTHREADS, SMEM_BYTES>>>();
    k_epilogue<<<NROWS / 64, 256>>>(W, b, out);
}